// round 14
// baseline (speedup 1.0000x reference)
#include <cuda_runtime.h>
#include <cstdint>

// Problem shape (fixed by setup_inputs)
#define BB 8
#define NN 2000
#define EE 20
#define HH 128
#define ROWS (BB * NN)        // 16000 node rows
#define NODES_PER_CTA 8
#define NTILE (NODES_PER_CTA * EE)   // 160 edge rows per tile (MMA N)
#define NTILES (ROWS / NODES_PER_CTA) // 2000
#define GRID_PERSIST 152              // 1 CTA per SM (GB300: 152 SMs)

// B smem: raw fp32, row-major [n][BSW words]. BSW=132 => row stride ≡ 4 mod 32
// banks; fragment LDS.32 bank = 4*gid + t4 = lane id -> conflict-free.
#define BSW 132
#define DS  164    // D smem stride (words): [128][160] f32, 16B multiple

// smem layout (bytes) for gemm_fused (double-buffered persistent)
#define B_BYTES   (NTILE * BSW * 4)      // 84480
#define SM_B0     0
#define SM_B1     B_BYTES                // 84480
#define SM_IDX0   (2 * B_BYTES)          // 168960
#define SM_IDX1   (SM_IDX0 + 1024)
#define SM_TOTAL  (SM_IDX1 + 1024)       // 171008 -> 1 CTA/SM
// D reuses the current B buffer: 128*164*4 = 83968 <= 84480

// Scratch (static device arrays — no runtime allocation)
__device__ float g_Ux[ROWS * HH];
__device__ float g_Vx[ROWS * HH];
// We as A-fragments: [kstep16][mtile8][lane32] uint4 {a0,a1,a2,a3}
__device__ uint4 g_WeFrag[16 * 8 * 32];
// Wu/Wv as B-fragments: [mat2][kstep16][ntile16][lane32] uint2 {b0,b1}
__device__ uint2 g_WFrag[2 * 16 * 16 * 32];

__device__ __forceinline__ uint32_t to_tf32(float f) {
    uint32_t r; asm("cvt.rna.tf32.f32 %0, %1;" : "=r"(r) : "f"(f)); return r;
}

// m16n8k8 tf32 warp MMA (family-portable; tcgen05 unavailable on sm_103 base)
__device__ __forceinline__ void mma_tf32(float d[4], const uint32_t a[4],
                                         const uint32_t b[2]) {
    asm volatile(
        "mma.sync.aligned.m16n8k8.row.col.f32.tf32.tf32.f32 "
        "{%0,%1,%2,%3}, {%4,%5,%6,%7}, {%8,%9}, {%0,%1,%2,%3};"
        : "+f"(d[0]), "+f"(d[1]), "+f"(d[2]), "+f"(d[3])
        : "r"(a[0]), "r"(a[1]), "r"(a[2]), "r"(a[3]), "r"(b[0]), "r"(b[1]));
}

// cp.async 16B (LDGSTS, sm_80+ family-portable)
__device__ __forceinline__ void cp_async16(uint32_t smem_dst, const void* gsrc) {
    asm volatile("cp.async.ca.shared.global [%0], [%1], 16;"
                 :: "r"(smem_dst), "l"(gsrc) : "memory");
}
__device__ __forceinline__ void cp_commit() {
    asm volatile("cp.async.commit_group;" ::: "memory");
}
__device__ __forceinline__ void cp_wait0() {
    asm volatile("cp.async.wait_group 0;" ::: "memory");
}
__device__ __forceinline__ void cp_wait1() {
    asm volatile("cp.async.wait_group 1;" ::: "memory");
}

// ---------------------------------------------------------------------------
// build_frags: one kernel builds all three fragment tables.
// ---------------------------------------------------------------------------
__global__ void build_frags(const float* __restrict__ We,
                            const float* __restrict__ Wu,
                            const float* __restrict__ Wv)
{
    const int id = blockIdx.x * 256 + threadIdx.x;   // grid 80 x 256 = 20480
    const int lane = id & 31;
    const int gid = lane >> 2, t4 = lane & 3;
    if (id < 4096) {
        const int blk = id >> 5;          // ks*8 + mtile
        const int s = blk >> 3, mtile = blk & 7;
        const int m = mtile * 16 + gid;
        const int k = s * 8 + t4;
        uint4 w;
        w.x = to_tf32(We[(size_t)k * HH + m]);
        w.y = to_tf32(We[(size_t)k * HH + m + 8]);
        w.z = to_tf32(We[(size_t)(k + 4) * HH + m]);
        w.w = to_tf32(We[(size_t)(k + 4) * HH + m + 8]);
        g_WeFrag[blk * 32 + lane] = w;
    } else {
        const int mat = (id < 12288) ? 0 : 1;
        const float* W = mat ? Wv : Wu;
        const int idx = id - 4096 - mat * 8192;   // (ks*16+nt)*32 + lane
        const int blk = idx >> 5;                 // ks*16 + nt
        const int ks = blk >> 4, nt = blk & 15;
        const int n = nt * 8 + gid;
        const int k = ks * 8 + t4;
        uint2 w;
        w.x = to_tf32(W[(size_t)k * HH + n]);
        w.y = to_tf32(W[(size_t)(k + 4) * HH + n]);
        g_WFrag[mat * 8192 + blk * 32 + lane] = w;
    }
}

// ---------------------------------------------------------------------------
// linear_mma: Ux = x@Wu+bu AND Vx = x@Wv+bv via m16n8k8 tf32.
// Grid 250 (64 rows/CTA), 256 threads: warp = (mat = wid>>2, mtile = wid&3).
// ---------------------------------------------------------------------------
__global__ __launch_bounds__(256, 2) void linear_mma(
    const float* __restrict__ x,
    const float* __restrict__ bu, const float* __restrict__ bv)
{
    __shared__ __align__(16) uint32_t xs[64 * BSW];   // 33792 B

    const int t = threadIdx.x;
    const int lane = t & 31;
    const int wid = t >> 5;
    const int gid = lane >> 2, t4 = lane & 3;
    const int row0 = blockIdx.x * 64;

    {
        const float4* src = (const float4*)(x + (size_t)row0 * HH);
        const uint32_t sb = (uint32_t)__cvta_generic_to_shared(xs);
        #pragma unroll
        for (int it = 0; it < 8; it++) {
            int i = t + it * 256;
            int r = i >> 5, q = i & 31;
            cp_async16(sb + (r * BSW + q * 4) * 4, src + i);
        }
    }
    cp_commit();
    cp_wait0();
    __syncthreads();

    const int mat = wid >> 2;
    const int m0 = (wid & 3) * 16;

    float d[16][4];
    #pragma unroll
    for (int nt = 0; nt < 16; nt++)
        #pragma unroll
        for (int c = 0; c < 4; c++) d[nt][c] = 0.f;

    const uint2* wf_base = g_WFrag + mat * 8192 + lane;

    #pragma unroll 1
    for (int ks = 0; ks < 16; ks++) {
        const uint32_t* rA = xs + (m0 + gid) * BSW + ks * 8 + t4;
        const uint32_t* rB = xs + (m0 + 8 + gid) * BSW + ks * 8 + t4;
        uint32_t a[4];
        a[0] = to_tf32(__uint_as_float(rA[0]));
        a[1] = to_tf32(__uint_as_float(rB[0]));
        a[2] = to_tf32(__uint_as_float(rA[4]));
        a[3] = to_tf32(__uint_as_float(rB[4]));
        const uint2* wf = wf_base + (size_t)ks * 16 * 32;
        uint32_t b[16][2];
        #pragma unroll
        for (int nt = 0; nt < 16; nt++) {
            uint2 bb = wf[nt * 32];
            b[nt][0] = bb.x; b[nt][1] = bb.y;
        }
        #pragma unroll
        for (int nt = 0; nt < 16; nt++)
            mma_tf32(d[nt], a, b[nt]);
    }

    float* out = mat ? g_Vx : g_Ux;
    const float* bias = mat ? bv : bu;
    const int r0 = row0 + m0 + gid;
    #pragma unroll
    for (int nt = 0; nt < 16; nt++) {
        const int col = nt * 8 + t4 * 2;
        const float2 b2 = *(const float2*)(bias + col);
        *(float2*)(out + (size_t)r0 * HH + col) =
            make_float2(d[nt][0] + b2.x, d[nt][1] + b2.y);
        *(float2*)(out + (size_t)(r0 + 8) * HH + col) =
            make_float2(d[nt][2] + b2.x, d[nt][3] + b2.y);
    }
}

// ---------------------------------------------------------------------------
// gemm_fused: PERSISTENT, grid=152, 1 CTA/SM, double-buffered tile pipeline.
//   Per tile (8 nodes): prefetch next tile's B (cp.async) -> MMA current ->
//   D->smem -> softmax/gather/add epilogue. Next tile's DRAM stream overlaps
//   the whole compute phase. (be dropped: softmax over E shift-invariant.)
// ---------------------------------------------------------------------------
__global__ __launch_bounds__(256, 1) void gemm_fused(
    const float* __restrict__ e,
    const int* __restrict__ edge_index,
    float* __restrict__ out)
{
    extern __shared__ __align__(16) char smem[];
    const uint32_t sb = (uint32_t)__cvta_generic_to_shared(smem);

    const int t = threadIdx.x;
    const int lane = t & 31;
    const int wid = t >> 5;
    const int gid = lane >> 2, t4 = lane & 3;

    // Warp tile: 4 warps over M=128 (32 each), 2 warps over N=160 (80 each)
    const int m0 = (wid & 3) * 32;
    const int n0 = (wid >> 2) * 80;
    const int mtile0 = (wid & 3) * 2;

    const uint32_t boff[2] = {SM_B0, SM_B1};
    const uint32_t ioff[2] = {SM_IDX0, SM_IDX1};

    // ---- prologue: load first tile into buffer 0
    int tile = blockIdx.x;
    if (tile < NTILES) {
        const float4* src = (const float4*)(e + (size_t)tile * NTILE * HH);
        #pragma unroll
        for (int it = 0; it < 20; it++) {
            int i = t + it * 256;
            int n = i >> 5, q = i & 31;
            cp_async16(sb + SM_B0 + (n * BSW + q * 4) * 4, src + i);
        }
        if (t < 40)
            cp_async16(sb + SM_IDX0 + t * 16,
                       (const float4*)(edge_index + (size_t)tile * NTILE) + t);
    }
    cp_commit();

    int cur = 0;
    while (tile < NTILES) {
        const int next_tile = tile + GRID_PERSIST;
        const bool has_next = next_tile < NTILES;

        // ---- prefetch next tile into the spare buffer
        if (has_next) {
            const int nx = cur ^ 1;
            const float4* src = (const float4*)(e + (size_t)next_tile * NTILE * HH);
            #pragma unroll
            for (int it = 0; it < 20; it++) {
                int i = t + it * 256;
                int n = i >> 5, q = i & 31;
                cp_async16(sb + boff[nx] + (n * BSW + q * 4) * 4, src + i);
            }
            if (t < 40)
                cp_async16(sb + ioff[nx] + t * 16,
                           (const float4*)(edge_index + (size_t)next_tile * NTILE) + t);
            cp_commit();
            cp_wait1();     // current tile's group complete
        } else {
            cp_wait0();
        }
        __syncthreads();

        uint32_t* Bw = (uint32_t*)(smem + boff[cur]);
        float* Ds = (float*)(smem + boff[cur]);      // reuses B after MMA
        const int* idx_s = (const int*)(smem + ioff[cur]);
        const int node0 = tile * NODES_PER_CTA;

        // ---- MMA
        float d[2][10][4];
        #pragma unroll
        for (int mt = 0; mt < 2; mt++)
            #pragma unroll
            for (int j = 0; j < 10; j++)
                #pragma unroll
                for (int c = 0; c < 4; c++) d[mt][j][c] = 0.f;

        #pragma unroll 1
        for (int ks = 0; ks < 16; ks++) {
            uint32_t a[2][4];
            #pragma unroll
            for (int mt = 0; mt < 2; mt++) {
                const uint4 af = g_WeFrag[(ks * 8 + mtile0 + mt) * 32 + lane];
                a[mt][0] = af.x; a[mt][1] = af.y; a[mt][2] = af.z; a[mt][3] = af.w;
            }
            const uint32_t* brow = Bw + (n0 + gid) * BSW + ks * 8 + t4;
            uint32_t b[10][2];
            #pragma unroll
            for (int j = 0; j < 10; j++) {
                b[j][0] = to_tf32(__uint_as_float(brow[j * 8 * BSW]));
                b[j][1] = to_tf32(__uint_as_float(brow[j * 8 * BSW + 4]));
            }
            #pragma unroll
            for (int mt = 0; mt < 2; mt++)
                #pragma unroll
                for (int j = 0; j < 10; j++)
                    mma_tf32(d[mt][j], a[mt], b[j]);
        }

        __syncthreads();   // all fragment reads done before overwriting with D

        // ---- D fragments -> Ds[h][n] (row-major, stride DS)
        #pragma unroll
        for (int mt = 0; mt < 2; mt++) {
            const int row = m0 + mt * 16 + gid;
            #pragma unroll
            for (int j = 0; j < 10; j++) {
                const int col = n0 + 8 * j + 2 * t4;
                *(float2*)(Ds + row * DS + col)       = make_float2(d[mt][j][0], d[mt][j][1]);
                *(float2*)(Ds + (row + 8) * DS + col) = make_float2(d[mt][j][2], d[mt][j][3]);
            }
        }
        __syncthreads();

        // ---- epilogue: 1024 (h, node) tasks over 256 threads
        #pragma unroll
        for (int it = 0; it < 4; it++) {
            const int task = it * 256 + t;
            const int g = task >> 7;          // node in tile 0..7
            const int h = task & 127;         // channel

            const float4* vp = (const float4*)(Ds + h * DS + g * EE);
            float v[EE];
            #pragma unroll
            for (int c = 0; c < 5; c++) {
                float4 q = vp[c];
                v[4 * c] = q.x; v[4 * c + 1] = q.y; v[4 * c + 2] = q.z; v[4 * c + 3] = q.w;
            }

            float m = v[0];
            #pragma unroll
            for (int i = 1; i < EE; i++) m = fmaxf(m, v[i]);
            float s = 0.f;
            #pragma unroll
            for (int i = 0; i < EE; i++) { v[i] = __expf(v[i] - m); s += v[i]; }
            const float inv = 1.f / s;

            const int node = node0 + g;
            const int b = node / NN;
            const float* vxb = g_Vx + (size_t)b * NN * HH + h;
            float acc = 0.f;
            #pragma unroll
            for (int i = 0; i < EE; i++)
                acc += v[i] * vxb[(size_t)idx_s[g * EE + i] * HH];

            out[(size_t)node * HH + h] = g_Ux[(size_t)node * HH + h] + acc * inv;
        }
        __syncthreads();   // epilogue reads done before buf reused for prefetch

        tile = next_tile;
        cur ^= 1;
    }
}

// ---------------------------------------------------------------------------
// Launch. Inputs: x, e, Wu, bu, Wv, bv, We, be, edge_index, n_edges
// ---------------------------------------------------------------------------
extern "C" void kernel_launch(void* const* d_in, const int* in_sizes, int n_in,
                              void* d_out, int out_size)
{
    const float* x   = (const float*)d_in[0];
    const float* e   = (const float*)d_in[1];
    const float* Wu  = (const float*)d_in[2];
    const float* bu  = (const float*)d_in[3];
    const float* Wv  = (const float*)d_in[4];
    const float* bv  = (const float*)d_in[5];
    const float* We  = (const float*)d_in[6];
    // be (d_in[7]) irrelevant: softmax over E is shift-invariant per (n,h).
    const int* edge_index = (const int*)d_in[8];
    float* out = (float*)d_out;

    (void)in_sizes; (void)n_in; (void)out_size;

    // Idempotent, called every launch (no call-count guards).
    cudaFuncSetAttribute(gemm_fused,
                         cudaFuncAttributeMaxDynamicSharedMemorySize, SM_TOTAL);

    build_frags<<<80, 256>>>(We, Wu, Wv);
    linear_mma<<<ROWS / 64, 256>>>(x, bu, bv);
    gemm_fused<<<GRID_PERSIST, 256, SM_TOTAL>>>(e, edge_index, out);
}